// round 1
// baseline (speedup 1.0000x reference)
#include <cuda_runtime.h>

#define AN 100000
#define DIM 512
#define AFD 133
#define BFD 14

// ---------------- scratch (device globals: allocation-free rule) ----------------
__device__ float g_msg[(size_t)AN * DIM];
__device__ float g_self[(size_t)AN * DIM];
__device__ float g_t1[(size_t)AN * DIM];
__device__ float g_t2[(size_t)AN * DIM];
__device__ float g_cc[(size_t)AN * DIM];
__device__ float g_bp[(size_t)AN * DIM];   // bond_part = relu(nei_bond_sum)@Wh0_w[512:526] + Wh0_b
__device__ float g_nbs[(size_t)AN * 16];   // relu'd bond sums, padded 14->16

// ---------------- f32x2 packed-FMA helpers (PTX-only on sm_103a) ----------------
typedef unsigned long long u64;
__device__ __forceinline__ u64 pk2(float x, float y) {
    u64 r; asm("mov.b64 %0,{%1,%2};" : "=l"(r) : "f"(x), "f"(y)); return r;
}
__device__ __forceinline__ u64 ffma2(u64 a, u64 b, u64 c) {
    u64 d; asm("fma.rn.f32x2 %0,%1,%2,%3;" : "=l"(d) : "l"(a), "l"(b), "l"(c)); return d;
}
__device__ __forceinline__ void upk2(u64 v, float& x, float& y) {
    asm("mov.b64 {%0,%1},%2;" : "=f"(x), "=f"(y) : "l"(v));
}

// ---------------- small kernels ----------------
__global__ void k_zero(float* p, int n) {
    int t = blockIdx.x * blockDim.x + threadIdx.x;
    if (t < n) p[t] = 0.f;
}

__global__ void k_bond_sum(const float* __restrict__ fb, const int* __restrict__ a2b) {
    int t = blockIdx.x * blockDim.x + threadIdx.x;
    int atom = t >> 4, lane = t & 15;
    if (atom >= AN) return;
    float s = 0.f;
    if (lane < BFD) {
#pragma unroll
        for (int j = 0; j < 6; j++) {
            int b = a2b[atom * 6 + j];
            s += fb[(size_t)b * BFD + lane];
        }
        s = fmaxf(s, 0.f);
    }
    g_nbs[(size_t)atom * 16 + lane] = s;
}

__global__ void k_bp(const float* __restrict__ w, const float* __restrict__ b) {
    int t = blockIdx.x * blockDim.x + threadIdx.x;
    if (t >= AN * DIM) return;
    int r = t >> 9, c = t & 511;
    float acc = b[c];
#pragma unroll
    for (int k = 0; k < BFD; k++)
        acc += g_nbs[(size_t)r * 16 + k] * w[(size_t)(512 + k) * DIM + c];
    g_bp[t] = acc;
}

template <bool RELU>
__global__ void k_gather(const float* __restrict__ src, const int* __restrict__ a2a,
                         float* __restrict__ dst) {
    int atom = blockIdx.x;
    __shared__ int si[6];
    if (threadIdx.x < 6) si[threadIdx.x] = a2a[atom * 6 + threadIdx.x];
    __syncthreads();
    int c = threadIdx.x << 2;
    float x = 0.f, y = 0.f, z = 0.f, w = 0.f;
#pragma unroll
    for (int j = 0; j < 6; j++) {
        const float4 v = *reinterpret_cast<const float4*>(&src[(size_t)si[j] * DIM + c]);
        x += v.x; y += v.y; z += v.z; w += v.w;
    }
    if (RELU) { x = fmaxf(x, 0.f); y = fmaxf(y, 0.f); z = fmaxf(z, 0.f); w = fmaxf(w, 0.f); }
    float4 o = make_float4(x, y, z, w);
    *reinterpret_cast<float4*>(&dst[(size_t)atom * DIM + c]) = o;
}

// ---------------- main GEMM ----------------
// MODE 0: C = relu(acc + bias_vec)
// MODE 1: C = relu(acc + bmat[r,c])
// MODE 2: v = C2 + acc + bias; C2 = v; C = (r==0?0:v)
// MODE 3: v = relu(acc + bias); r==0 -> 0; C = v; C2 = v
// MODE 4: v = relu(acc + bias); atomicAdd(out[mol[r]*512+c], v)
template <int MODE>
__global__ __launch_bounds__(256, 2) void k_gemm(
    const float* __restrict__ A, int lda, int K1,
    const float* __restrict__ A2, int K,
    const float* __restrict__ W,
    const float* __restrict__ bias, const float* __restrict__ bmat,
    float* __restrict__ C, float* __restrict__ C2,
    const int* __restrict__ mol, int nm, float* __restrict__ outp, int M)
{
    __shared__ float As[16][132];
    __shared__ float Ws[16][68];
    const int tid = threadIdx.x;
    const int tx = tid & 15, ty = tid >> 4;
    const int n0 = blockIdx.x * 64, r0 = blockIdx.y * 128;

    u64 acc[8][2];
#pragma unroll
    for (int i = 0; i < 8; i++) { acc[i][0] = 0ull; acc[i][1] = 0ull; }

    const int arow = tid >> 1, kb = (tid & 1) << 3;
    const int grl = r0 + arow;
    const int kk = tid >> 4, c4 = (tid & 15) << 2;

    for (int k0 = 0; k0 < K; k0 += 16) {
#pragma unroll
        for (int i = 0; i < 8; i++) {
            int k = k0 + kb + i;
            float v = 0.f;
            if (grl < M && k < K)
                v = (k < K1) ? A[(size_t)grl * lda + k]
                             : A2[(size_t)grl * DIM + (k - K1)];
            As[kb + i][arow] = v;
        }
        int gk = k0 + kk;
        float4 wv = make_float4(0.f, 0.f, 0.f, 0.f);
        if (gk < K)
            wv = *reinterpret_cast<const float4*>(&W[(size_t)gk * DIM + n0 + c4]);
        *reinterpret_cast<float4*>(&Ws[kk][c4]) = wv;
        __syncthreads();

#pragma unroll
        for (int k = 0; k < 16; k++) {
            float4 wq = *reinterpret_cast<float4*>(&Ws[k][tx << 2]);
            u64 w0 = pk2(wq.x, wq.y), w1 = pk2(wq.z, wq.w);
            float4 a0 = *reinterpret_cast<float4*>(&As[k][ty << 3]);
            float4 a1 = *reinterpret_cast<float4*>(&As[k][(ty << 3) + 4]);
            float ar[8] = {a0.x, a0.y, a0.z, a0.w, a1.x, a1.y, a1.z, a1.w};
#pragma unroll
            for (int i = 0; i < 8; i++) {
                u64 aa = pk2(ar[i], ar[i]);
                acc[i][0] = ffma2(aa, w0, acc[i][0]);
                acc[i][1] = ffma2(aa, w1, acc[i][1]);
            }
        }
        __syncthreads();
    }

    const int gcb = n0 + (tx << 2);
    float4 bv = make_float4(0.f, 0.f, 0.f, 0.f);
    if (MODE != 1) bv = *reinterpret_cast<const float4*>(&bias[gcb]);

#pragma unroll
    for (int i = 0; i < 8; i++) {
        int gr = r0 + (ty << 3) + i;
        if (gr >= M) break;
        float v0, v1, v2, v3;
        upk2(acc[i][0], v0, v1);
        upk2(acc[i][1], v2, v3);
        size_t co = (size_t)gr * DIM + gcb;

        if (MODE == 0) {
            float4 o = make_float4(fmaxf(v0 + bv.x, 0.f), fmaxf(v1 + bv.y, 0.f),
                                   fmaxf(v2 + bv.z, 0.f), fmaxf(v3 + bv.w, 0.f));
            *reinterpret_cast<float4*>(&C[co]) = o;
        } else if (MODE == 1) {
            float4 bm = *reinterpret_cast<const float4*>(&bmat[co]);
            float4 o = make_float4(fmaxf(v0 + bm.x, 0.f), fmaxf(v1 + bm.y, 0.f),
                                   fmaxf(v2 + bm.z, 0.f), fmaxf(v3 + bm.w, 0.f));
            *reinterpret_cast<float4*>(&C[co]) = o;
        } else if (MODE == 2) {
            float4 s = *reinterpret_cast<float4*>(&C2[co]);
            float4 val = make_float4(s.x + v0 + bv.x, s.y + v1 + bv.y,
                                     s.z + v2 + bv.z, s.w + v3 + bv.w);
            *reinterpret_cast<float4*>(&C2[co]) = val;
            float4 m = val;
            if (gr == 0) m = make_float4(0.f, 0.f, 0.f, 0.f);
            *reinterpret_cast<float4*>(&C[co]) = m;
        } else if (MODE == 3) {
            float4 o = make_float4(fmaxf(v0 + bv.x, 0.f), fmaxf(v1 + bv.y, 0.f),
                                   fmaxf(v2 + bv.z, 0.f), fmaxf(v3 + bv.w, 0.f));
            if (gr == 0) o = make_float4(0.f, 0.f, 0.f, 0.f);
            *reinterpret_cast<float4*>(&C[co]) = o;
            *reinterpret_cast<float4*>(&C2[co]) = o;
        } else if (MODE == 4) {
            int mid = mol[gr];
            if (mid < nm) {
                float* dst = &outp[(size_t)mid * DIM + gcb];
                atomicAdd(dst + 0, fmaxf(v0 + bv.x, 0.f));
                atomicAdd(dst + 1, fmaxf(v1 + bv.y, 0.f));
                atomicAdd(dst + 2, fmaxf(v2 + bv.z, 0.f));
                atomicAdd(dst + 3, fmaxf(v3 + bv.w, 0.f));
            }
        }
    }
}

// ---------------- launch ----------------
extern "C" void kernel_launch(void* const* d_in, const int* in_sizes, int n_in,
                              void* d_out, int out_size) {
    const float* f_atoms = (const float*)d_in[0];
    const float* f_bonds = (const float*)d_in[1];
    const int*   a2a     = (const int*)d_in[2];
    const int*   a2b     = (const int*)d_in[3];
    const int*   mol_ids = (const int*)d_in[4];

    int base = 5;
    if (in_sizes[5] == 1) base = 6;   // n_mols materialized as scalar input
    const float* W_i_w  = (const float*)d_in[base + 0];
    const float* W_i_b  = (const float*)d_in[base + 1];
    const float* Wh0_w  = (const float*)d_in[base + 2];
    const float* Wh0_b  = (const float*)d_in[base + 3];
    const float* Wh1_w  = (const float*)d_in[base + 4];
    const float* Wh1_b  = (const float*)d_in[base + 5];
    const float* Wh2_w  = (const float*)d_in[base + 6];
    const float* Wh2_b  = (const float*)d_in[base + 7];
    const float* Wah0_w = (const float*)d_in[base + 8];
    const float* Wah0_b = (const float*)d_in[base + 9];
    const float* Wah1_w = (const float*)d_in[base + 10];
    const float* Wah1_b = (const float*)d_in[base + 11];
    const float* Wah2_w = (const float*)d_in[base + 12];
    const float* Wah2_b = (const float*)d_in[base + 13];
    const float* W_o_w  = (const float*)d_in[base + 14];
    const float* W_o_b  = (const float*)d_in[base + 15];

    float* out = (float*)d_out;
    int nm = out_size / DIM;

    float *msg, *self, *t1, *t2, *cc, *bp;
    cudaGetSymbolAddress((void**)&msg,  g_msg);
    cudaGetSymbolAddress((void**)&self, g_self);
    cudaGetSymbolAddress((void**)&t1,   g_t1);
    cudaGetSymbolAddress((void**)&t2,   g_t2);
    cudaGetSymbolAddress((void**)&cc,   g_cc);
    cudaGetSymbolAddress((void**)&bp,   g_bp);

    const int M = AN;
    dim3 gg(DIM / 64, (M + 127) / 128);
    dim3 gb(256);

    k_zero<<<(out_size + 255) / 256, 256>>>(out, out_size);
    k_bond_sum<<<(AN * 16 + 255) / 256, 256>>>(f_bonds, a2b);
    k_bp<<<(AN * DIM + 255) / 256, 256>>>(Wh0_w, Wh0_b);

    // msg = self = zero_row0(relu(f_atoms @ W_i + b))
    k_gemm<3><<<gg, gb>>>(f_atoms, AFD, AFD, nullptr, AFD, W_i_w,
                          W_i_b, nullptr, msg, self, nullptr, 0, nullptr, M);

    for (int d = 0; d < 4; d++) {
        k_gather<true><<<AN, 128>>>(msg, a2a, t1);
        k_gemm<1><<<gg, gb>>>(t1, DIM, DIM, nullptr, DIM, Wh0_w,
                              nullptr, bp, t2, nullptr, nullptr, 0, nullptr, M);
        k_gemm<0><<<gg, gb>>>(t2, DIM, DIM, nullptr, DIM, Wh1_w,
                              Wh1_b, nullptr, t1, nullptr, nullptr, 0, nullptr, M);
        k_gemm<2><<<gg, gb>>>(t1, DIM, DIM, nullptr, DIM, Wh2_w,
                              Wh2_b, nullptr, msg, self, nullptr, 0, nullptr, M);
    }

    k_gather<false><<<AN, 128>>>(msg, a2a, t1);

    k_gemm<0><<<gg, gb>>>(f_atoms, AFD, AFD, nullptr, AFD, Wah0_w,
                          Wah0_b, nullptr, cc, nullptr, nullptr, 0, nullptr, M);
    k_gemm<0><<<gg, gb>>>(cc, DIM, DIM, nullptr, DIM, Wah1_w,
                          Wah1_b, nullptr, t2, nullptr, nullptr, 0, nullptr, M);
    k_gemm<0><<<gg, gb>>>(t2, DIM, DIM, nullptr, DIM, Wah2_w,
                          Wah2_b, nullptr, cc, nullptr, nullptr, 0, nullptr, M);

    k_gemm<4><<<gg, gb>>>(cc, DIM, DIM, t1, 2 * DIM, W_o_w,
                          W_o_b, nullptr, nullptr, nullptr, mol_ids, nm, out, M);
}

// round 3
// speedup vs baseline: 2.7457x; 2.7457x over previous
#include <cuda_runtime.h>
#include <cuda_bf16.h>
#include <cstdint>

#define AN 100000
#define DIM 512
#define AFD 133
#define BFD 14
#define FAP 192          // padded K for f_atoms (6 chunks of 32)
#define WOP 1024
#define MBLK ((AN + 127) / 128)

typedef unsigned int u32; typedef unsigned short u16;

// ---------------- device-global scratch (allocation-free rule) ----------------
__device__ float g_msg[(size_t)AN * DIM];
__device__ float g_self[(size_t)AN * DIM];
__device__ float g_bp[(size_t)AN * DIM];
__device__ float g_nbs[(size_t)AN * 16];
__device__ u16 g_p1h[(size_t)AN * DIM], g_p1l[(size_t)AN * DIM];
__device__ u16 g_p2h[(size_t)AN * DIM], g_p2l[(size_t)AN * DIM];
__device__ u16 g_p3h[(size_t)AN * DIM], g_p3l[(size_t)AN * DIM];
__device__ u16 g_fah[(size_t)AN * FAP], g_fal[(size_t)AN * FAP];
// weight planes, K-major (B^T): WT[n][k] = W[k][n], bf16 hi/lo
__device__ u16 g_wih[512 * FAP],  g_wil[512 * FAP];
__device__ u16 g_w0h[512 * 512],  g_w0l[512 * 512];
__device__ u16 g_w1h[512 * 512],  g_w1l[512 * 512];
__device__ u16 g_w2h[512 * 512],  g_w2l[512 * 512];
__device__ u16 g_wa0h[512 * FAP], g_wa0l[512 * FAP];
__device__ u16 g_wa1h[512 * 512], g_wa1l[512 * 512];
__device__ u16 g_wa2h[512 * 512], g_wa2l[512 * 512];
__device__ u16 g_woh[512 * WOP],  g_wol[512 * WOP];

// ---------------- helpers ----------------
__device__ __forceinline__ u32 smem_u32(const void* p) {
    u32 a; asm("{ .reg .u64 t; cvta.to.shared.u64 t, %1; cvt.u32.u64 %0, t; }" : "=r"(a) : "l"(p));
    return a;
}
__device__ __forceinline__ void ldmA(u32 a[4], u32 addr) {
    asm volatile("ldmatrix.sync.aligned.m8n8.x4.shared.b16 {%0,%1,%2,%3},[%4];"
                 : "=r"(a[0]), "=r"(a[1]), "=r"(a[2]), "=r"(a[3]) : "r"(addr));
}
__device__ __forceinline__ void ldmB(u32 b[2], u32 addr) {
    asm volatile("ldmatrix.sync.aligned.m8n8.x2.shared.b16 {%0,%1},[%2];"
                 : "=r"(b[0]), "=r"(b[1]) : "r"(addr));
}
__device__ __forceinline__ void mma_bf16(float c[4], const u32 a[4], const u32 b[2]) {
    asm volatile("mma.sync.aligned.m16n8k16.row.col.f32.bf16.bf16.f32 "
                 "{%0,%1,%2,%3},{%4,%5,%6,%7},{%8,%9},{%0,%1,%2,%3};"
                 : "+f"(c[0]), "+f"(c[1]), "+f"(c[2]), "+f"(c[3])
                 : "r"(a[0]), "r"(a[1]), "r"(a[2]), "r"(a[3]), "r"(b[0]), "r"(b[1]));
}
__device__ __forceinline__ void split_bf16(float v, u16& h, u16& l) {
    __nv_bfloat16 hb = __float2bfloat16(v);
    float r = v - __bfloat162float(hb);
    h = __bfloat16_as_ushort(hb);
    l = __bfloat16_as_ushort(__float2bfloat16(r));
}

// ---------------- small kernels ----------------
__global__ void k_zero(float* p, int n) {
    int t = blockIdx.x * blockDim.x + threadIdx.x;
    if (t < n) p[t] = 0.f;
}

__global__ void k_bond_sum(const float* __restrict__ fb, const int* __restrict__ a2b) {
    int t = blockIdx.x * blockDim.x + threadIdx.x;
    int atom = t >> 4, lane = t & 15;
    if (atom >= AN) return;
    float s = 0.f;
    if (lane < BFD) {
#pragma unroll
        for (int j = 0; j < 6; j++)
            s += fb[(size_t)a2b[atom * 6 + j] * BFD + lane];
        s = fmaxf(s, 0.f);
    }
    g_nbs[(size_t)atom * 16 + lane] = s;
}

__global__ void k_bp(const float* __restrict__ w, const float* __restrict__ b) {
    int t = blockIdx.x * blockDim.x + threadIdx.x;
    if (t >= AN * DIM) return;
    int r = t >> 9, c = t & 511;
    float acc = b[c];
#pragma unroll
    for (int k = 0; k < BFD; k++)
        acc += g_nbs[(size_t)r * 16 + k] * w[(size_t)(512 + k) * DIM + c];
    g_bp[t] = acc;
}

// transpose + split weights: WT[n][k] = W[k][n]
__global__ void k_wconv(const float* __restrict__ W, int K, int KP, u16* __restrict__ Bh, u16* __restrict__ Bl) {
    int t = blockIdx.x * blockDim.x + threadIdx.x;
    if (t >= 512 * KP) return;
    int n = t / KP, k = t - n * KP;
    float v = (k < K) ? W[(size_t)k * DIM + n] : 0.f;
    u16 h, l; split_bf16(v, h, l);
    Bh[t] = h; Bl[t] = l;
}

__global__ void k_aconv(const float* __restrict__ fa) {
    int t = blockIdx.x * blockDim.x + threadIdx.x;
    if (t >= AN * FAP) return;
    int r = t / FAP, c = t - r * FAP;
    float v = (c < AFD) ? fa[(size_t)r * AFD + c] : 0.f;
    u16 h, l; split_bf16(v, h, l);
    g_fah[t] = h; g_fal[t] = l;
}

// gather 6 neighbor rows, optional relu, emit bf16 hi/lo planes
template <bool RELU>
__global__ void k_gather_p(const float* __restrict__ src, const int* __restrict__ a2a,
                           u16* __restrict__ dh, u16* __restrict__ dl) {
    int atom = blockIdx.x;
    __shared__ int si[6];
    if (threadIdx.x < 6) si[threadIdx.x] = a2a[atom * 6 + threadIdx.x];
    __syncthreads();
    int c = threadIdx.x << 2;
    float x = 0.f, y = 0.f, z = 0.f, w = 0.f;
#pragma unroll
    for (int j = 0; j < 6; j++) {
        const float4 v = *reinterpret_cast<const float4*>(&src[(size_t)si[j] * DIM + c]);
        x += v.x; y += v.y; z += v.z; w += v.w;
    }
    if (RELU) { x = fmaxf(x, 0.f); y = fmaxf(y, 0.f); z = fmaxf(z, 0.f); w = fmaxf(w, 0.f); }
    u16 h0, l0, h1, l1, h2, l2, h3, l3;
    split_bf16(x, h0, l0); split_bf16(y, h1, l1); split_bf16(z, h2, l2); split_bf16(w, h3, l3);
    size_t o = (size_t)atom * DIM + c;
    *reinterpret_cast<uint2*>(&dh[o]) = make_uint2((u32)h0 | ((u32)h1 << 16), (u32)h2 | ((u32)h3 << 16));
    *reinterpret_cast<uint2*>(&dl[o]) = make_uint2((u32)l0 | ((u32)l1 << 16), (u32)l2 | ((u32)l3 << 16));
}

// ---------------- HMMA bf16x3 GEMM: C[128,128] per CTA ----------------
// MODE 0: planes = relu(acc + bias)
// MODE 1: planes = relu(acc + bmat)
// MODE 2: v = self + acc + bias; self=v; msg=(r==0?0:v)     (fp32 out)
// MODE 3: v = relu(acc + bias); r==0->0; msg=v; self=v      (fp32 out)
// MODE 4: v = relu(acc + bias); atomicAdd(out[mol[r]], v)
#define LDS_STRIDE 40   // u16 elements per smem row (32 + 8 pad)

template <int MODE>
__global__ __launch_bounds__(256, 2) void k_gemm_mma(
    const u16* __restrict__ Ah, const u16* __restrict__ Al, int ld1, int K1c,
    const u16* __restrict__ A2h, const u16* __restrict__ A2l, int ld2, int KC,
    const u16* __restrict__ Bh, const u16* __restrict__ Bl, int ldB,
    const float* __restrict__ bias, const float* __restrict__ bmat,
    u16* __restrict__ Ch, u16* __restrict__ Cl,
    float* __restrict__ Cf, float* __restrict__ C2f,
    const int* __restrict__ mol, int nm, float* __restrict__ outp, int M)
{
    __shared__ u16 sAh[128 * LDS_STRIDE], sAl[128 * LDS_STRIDE];
    __shared__ u16 sBh[128 * LDS_STRIDE], sBl[128 * LDS_STRIDE];

    const int tid = threadIdx.x;
    const int lane = tid & 31, wid = tid >> 5;
    const int wm = wid >> 2, wn = wid & 3;          // warp grid 2(M) x 4(N)
    const int mbase = wm * 64, nbase = wn * 32;     // warp tile 64x32
    const int n0 = blockIdx.x * 128, r0 = blockIdx.y * 128;
    const int g = lane >> 2, tig = lane & 3;

    float acc[4][4][4];
#pragma unroll
    for (int i = 0; i < 4; i++)
#pragma unroll
        for (int j = 0; j < 4; j++)
#pragma unroll
            for (int q = 0; q < 4; q++) acc[i][j][q] = 0.f;

    // ldmatrix per-lane base offsets (bytes)
    const int mtxa = lane >> 3;                 // 0..3
    const int a_row = (mtxa & 1) * 8 + (lane & 7);
    const int a_k   = (mtxa >> 1) * 8;
    const u32 aoff = (u32)((mbase + a_row) * LDS_STRIDE + a_k) * 2;
    const int mtxb = (lane >> 3) & 1;
    const u32 boff = (u32)((nbase + (lane & 7)) * LDS_STRIDE + mtxb * 8) * 2;

    const u32 sAh_b = smem_u32(sAh), sAl_b = smem_u32(sAl);
    const u32 sBh_b = smem_u32(sBh), sBl_b = smem_u32(sBl);

    // smem fill mapping: 64 rows per pass, 4 uint4 per row
    const int lrow = tid >> 2;
    const int lq = (tid & 3) * 8;   // u16 offset within 32-col row

    for (int kb = 0; kb < KC; kb++) {
        const u16* gAh; const u16* gAl; int acol, ldA;
        if (kb < K1c) { gAh = Ah;  gAl = Al;  acol = kb * 32;          ldA = ld1; }
        else          { gAh = A2h; gAl = A2l; acol = (kb - K1c) * 32;  ldA = ld2; }

        __syncthreads();
#pragma unroll
        for (int p = 0; p < 2; p++) {
            int row = p * 64 + lrow;
            int grow = r0 + row;
            uint4 vh = make_uint4(0, 0, 0, 0), vl = vh;
            if (grow < M) {
                vh = *reinterpret_cast<const uint4*>(&gAh[(size_t)grow * ldA + acol + lq]);
                vl = *reinterpret_cast<const uint4*>(&gAl[(size_t)grow * ldA + acol + lq]);
            }
            *reinterpret_cast<uint4*>(&sAh[row * LDS_STRIDE + lq]) = vh;
            *reinterpret_cast<uint4*>(&sAl[row * LDS_STRIDE + lq]) = vl;
            int brow = n0 + row;
            *reinterpret_cast<uint4*>(&sBh[row * LDS_STRIDE + lq]) =
                *reinterpret_cast<const uint4*>(&Bh[(size_t)brow * ldB + kb * 32 + lq]);
            *reinterpret_cast<uint4*>(&sBl[row * LDS_STRIDE + lq]) =
                *reinterpret_cast<const uint4*>(&Bl[(size_t)brow * ldB + kb * 32 + lq]);
        }
        __syncthreads();

#pragma unroll
        for (int ks = 0; ks < 2; ks++) {
            const u32 kby = (u32)ks * 32;   // 16 elems * 2B
            u32 ah[4][4], al[4][4];
#pragma unroll
            for (int fm = 0; fm < 4; fm++) {
                ldmA(ah[fm], sAh_b + aoff + (u32)fm * (16 * LDS_STRIDE * 2) + kby);
                ldmA(al[fm], sAl_b + aoff + (u32)fm * (16 * LDS_STRIDE * 2) + kby);
            }
#pragma unroll
            for (int fn = 0; fn < 4; fn++) {
                u32 bh[2], bl[2];
                ldmB(bh, sBh_b + boff + (u32)fn * (8 * LDS_STRIDE * 2) + kby);
                ldmB(bl, sBl_b + boff + (u32)fn * (8 * LDS_STRIDE * 2) + kby);
#pragma unroll
                for (int fm = 0; fm < 4; fm++) {
                    mma_bf16(acc[fm][fn], ah[fm], bh);
                    mma_bf16(acc[fm][fn], ah[fm], bl);
                    mma_bf16(acc[fm][fn], al[fm], bh);
                }
            }
        }
    }

    // ---------------- epilogue ----------------
#pragma unroll
    for (int fm = 0; fm < 4; fm++) {
#pragma unroll
        for (int half = 0; half < 2; half++) {
            const int gr = r0 + mbase + fm * 16 + g + half * 8;
            if (gr >= M) continue;
            int mid = 0;
            if (MODE == 4) mid = mol[gr];
#pragma unroll
            for (int fn = 0; fn < 4; fn++) {
                const int gc = n0 + nbase + fn * 8 + tig * 2;
                float v0 = acc[fm][fn][half * 2 + 0];
                float v1 = acc[fm][fn][half * 2 + 1];

                if (MODE == 1) {
                    float2 m2 = *reinterpret_cast<const float2*>(&bmat[(size_t)gr * DIM + gc]);
                    v0 += m2.x; v1 += m2.y;
                } else {
                    float2 b2 = *reinterpret_cast<const float2*>(&bias[gc]);
                    v0 += b2.x; v1 += b2.y;
                }

                if (MODE == 0 || MODE == 1) {
                    v0 = fmaxf(v0, 0.f); v1 = fmaxf(v1, 0.f);
                    u16 h0, l0, h1, l1;
                    split_bf16(v0, h0, l0); split_bf16(v1, h1, l1);
                    *reinterpret_cast<u32*>(&Ch[(size_t)gr * DIM + gc]) = (u32)h0 | ((u32)h1 << 16);
                    *reinterpret_cast<u32*>(&Cl[(size_t)gr * DIM + gc]) = (u32)l0 | ((u32)l1 << 16);
                } else if (MODE == 2) {
                    float2 s2 = *reinterpret_cast<const float2*>(&C2f[(size_t)gr * DIM + gc]);
                    v0 += s2.x; v1 += s2.y;
                    *reinterpret_cast<float2*>(&C2f[(size_t)gr * DIM + gc]) = make_float2(v0, v1);
                    if (gr == 0) { v0 = 0.f; v1 = 0.f; }
                    *reinterpret_cast<float2*>(&Cf[(size_t)gr * DIM + gc]) = make_float2(v0, v1);
                } else if (MODE == 3) {
                    v0 = fmaxf(v0, 0.f); v1 = fmaxf(v1, 0.f);
                    if (gr == 0) { v0 = 0.f; v1 = 0.f; }
                    *reinterpret_cast<float2*>(&Cf[(size_t)gr * DIM + gc]) = make_float2(v0, v1);
                    *reinterpret_cast<float2*>(&C2f[(size_t)gr * DIM + gc]) = make_float2(v0, v1);
                } else if (MODE == 4) {
                    if (mid < nm) {
                        float* dst = &outp[(size_t)mid * DIM + gc];
                        atomicAdd(dst + 0, fmaxf(v0, 0.f));
                        atomicAdd(dst + 1, fmaxf(v1, 0.f));
                    }
                }
            }
        }
    }
}

// ---------------- launch ----------------
extern "C" void kernel_launch(void* const* d_in, const int* in_sizes, int n_in,
                              void* d_out, int out_size) {
    const float* f_atoms = (const float*)d_in[0];
    const float* f_bonds = (const float*)d_in[1];
    const int*   a2a     = (const int*)d_in[2];
    const int*   a2b     = (const int*)d_in[3];
    const int*   mol_ids = (const int*)d_in[4];

    int base = 5;
    if (in_sizes[5] == 1) base = 6;
    const float* W_i_w  = (const float*)d_in[base + 0];
    const float* W_i_b  = (const float*)d_in[base + 1];
    const float* Wh0_w  = (const float*)d_in[base + 2];
    const float* Wh0_b  = (const float*)d_in[base + 3];
    const float* Wh1_w  = (const float*)d_in[base + 4];
    const float* Wh1_b  = (const float*)d_in[base + 5];
    const float* Wh2_w  = (const float*)d_in[base + 6];
    const float* Wh2_b  = (const float*)d_in[base + 7];
    const float* Wah0_w = (const float*)d_in[base + 8];
    const float* Wah0_b = (const float*)d_in[base + 9];
    const float* Wah1_w = (const float*)d_in[base + 10];
    const float* Wah1_b = (const float*)d_in[base + 11];
    const float* Wah2_w = (const float*)d_in[base + 12];
    const float* Wah2_b = (const float*)d_in[base + 13];
    const float* W_o_w  = (const float*)d_in[base + 14];
    const float* W_o_b  = (const float*)d_in[base + 15];

    float* out = (float*)d_out;
    int nm = out_size / DIM;

    float *msg, *self, *bp;
    u16 *p1h, *p1l, *p2h, *p2l, *p3h, *p3l, *fah, *fal;
    u16 *wih, *wil, *w0h, *w0l, *w1h, *w1l, *w2h, *w2l;
    u16 *wa0h, *wa0l, *wa1h, *wa1l, *wa2h, *wa2l, *woh, *wol;
    cudaGetSymbolAddress((void**)&msg, g_msg);   cudaGetSymbolAddress((void**)&self, g_self);
    cudaGetSymbolAddress((void**)&bp, g_bp);
    cudaGetSymbolAddress((void**)&p1h, g_p1h);   cudaGetSymbolAddress((void**)&p1l, g_p1l);
    cudaGetSymbolAddress((void**)&p2h, g_p2h);   cudaGetSymbolAddress((void**)&p2l, g_p2l);
    cudaGetSymbolAddress((void**)&p3h, g_p3h);   cudaGetSymbolAddress((void**)&p3l, g_p3l);
    cudaGetSymbolAddress((void**)&fah, g_fah);   cudaGetSymbolAddress((void**)&fal, g_fal);
    cudaGetSymbolAddress((void**)&wih, g_wih);   cudaGetSymbolAddress((void**)&wil, g_wil);
    cudaGetSymbolAddress((void**)&w0h, g_w0h);   cudaGetSymbolAddress((void**)&w0l, g_w0l);
    cudaGetSymbolAddress((void**)&w1h, g_w1h);   cudaGetSymbolAddress((void**)&w1l, g_w1l);
    cudaGetSymbolAddress((void**)&w2h, g_w2h);   cudaGetSymbolAddress((void**)&w2l, g_w2l);
    cudaGetSymbolAddress((void**)&wa0h, g_wa0h); cudaGetSymbolAddress((void**)&wa0l, g_wa0l);
    cudaGetSymbolAddress((void**)&wa1h, g_wa1h); cudaGetSymbolAddress((void**)&wa1l, g_wa1l);
    cudaGetSymbolAddress((void**)&wa2h, g_wa2h); cudaGetSymbolAddress((void**)&wa2l, g_wa2l);
    cudaGetSymbolAddress((void**)&woh, g_woh);   cudaGetSymbolAddress((void**)&wol, g_wol);

    const int M = AN;
    dim3 gg(4, MBLK);
    const int TB = 256;

    k_zero<<<(out_size + 255) / 256, 256>>>(out, out_size);
    k_bond_sum<<<(AN * 16 + 255) / 256, 256>>>(f_bonds, a2b);
    k_bp<<<(AN * DIM + 255) / 256, 256>>>(Wh0_w, Wh0_b);
    k_aconv<<<(AN * FAP + 255) / 256, 256>>>(f_atoms);
    k_wconv<<<(512 * FAP + 255) / 256, 256>>>(W_i_w, AFD, FAP, wih, wil);
    k_wconv<<<(512 * 512 + 255) / 256, 256>>>(Wh0_w, 512, 512, w0h, w0l);
    k_wconv<<<(512 * 512 + 255) / 256, 256>>>(Wh1_w, 512, 512, w1h, w1l);
    k_wconv<<<(512 * 512 + 255) / 256, 256>>>(Wh2_w, 512, 512, w2h, w2l);
    k_wconv<<<(512 * FAP + 255) / 256, 256>>>(Wah0_w, AFD, FAP, wa0h, wa0l);
    k_wconv<<<(512 * 512 + 255) / 256, 256>>>(Wah1_w, 512, 512, wa1h, wa1l);
    k_wconv<<<(512 * 512 + 255) / 256, 256>>>(Wah2_w, 512, 512, wa2h, wa2l);
    k_wconv<<<(512 * WOP + 255) / 256, 256>>>(W_o_w, WOP, WOP, woh, wol);

    // msg = self = zero_row0(relu(f_atoms @ W_i + b))
    k_gemm_mma<3><<<gg, TB>>>(fah, fal, FAP, 6, fah, fal, FAP, 6, wih, wil, FAP,
                              W_i_b, nullptr, nullptr, nullptr, msg, self,
                              nullptr, 0, nullptr, M);

    for (int d = 0; d < 4; d++) {
        k_gather_p<true><<<AN, 128>>>(msg, a2a, p1h, p1l);
        k_gemm_mma<1><<<gg, TB>>>(p1h, p1l, DIM, 16, p1h, p1l, DIM, 16, w0h, w0l, 512,
                                  nullptr, bp, p2h, p2l, nullptr, nullptr,
                                  nullptr, 0, nullptr, M);
        k_gemm_mma<0><<<gg, TB>>>(p2h, p2l, DIM, 16, p2h, p2l, DIM, 16, w1h, w1l, 512,
                                  Wh1_b, nullptr, p1h, p1l, nullptr, nullptr,
                                  nullptr, 0, nullptr, M);
        k_gemm_mma<2><<<gg, TB>>>(p1h, p1l, DIM, 16, p1h, p1l, DIM, 16, w2h, w2l, 512,
                                  Wh2_b, nullptr, nullptr, nullptr, msg, self,
                                  nullptr, 0, nullptr, M);
    }

    // cc chain: fa -> p2 -> p1 -> p3
    k_gemm_mma<0><<<gg, TB>>>(fah, fal, FAP, 6, fah, fal, FAP, 6, wa0h, wa0l, FAP,
                              Wah0_b, nullptr, p2h, p2l, nullptr, nullptr,
                              nullptr, 0, nullptr, M);
    k_gemm_mma<0><<<gg, TB>>>(p2h, p2l, DIM, 16, p2h, p2l, DIM, 16, wa1h, wa1l, 512,
                              Wah1_b, nullptr, p1h, p1l, nullptr, nullptr,
                              nullptr, 0, nullptr, M);
    k_gemm_mma<0><<<gg, TB>>>(p1h, p1l, DIM, 16, p1h, p1l, DIM, 16, wa2h, wa2l, 512,
                              Wah2_b, nullptr, p3h, p3l, nullptr, nullptr,
                              nullptr, 0, nullptr, M);

    // a_message (no relu) -> p2 planes
    k_gather_p<false><<<AN, 128>>>(msg, a2a, p2h, p2l);

    // out = relu([cc, am] @ W_o + b), fused segment-sum
    k_gemm_mma<4><<<gg, TB>>>(p3h, p3l, DIM, 16, p2h, p2l, DIM, 32, woh, wol, WOP,
                              W_o_b, nullptr, nullptr, nullptr, nullptr, nullptr,
                              mol_ids, nm, out, M);
}